// round 3
// baseline (speedup 1.0000x reference)
#include <cuda_runtime.h>
#include <cuda_bf16.h>
#include <cstdint>

// Problem constants
#define NN      131072
#define FF      512
#define EE      2097152
#define DA      16
#define NPOOL   65536
#define FP      256
#define NB      65536       // buckets = pooled row (key >> 16)
#define MAXB    128         // max bucket size (Poisson mean 32; tail ~1e-15)

// Output layout (float elements, single concatenated array)
#define X_OFF   0ull
#define EI_OFF  16777216ull                              // 65536*256
#define EA_OFF  (EI_OFF + 2ull*EE)                       // 20971520
#define BP_OFF  (EA_OFF + (unsigned long long)EE*DA)     // 54525952

// ---------------- scratch ----------------------------------------------------
__device__ unsigned            g_keys[EE];     // 8 MB
__device__ unsigned long long  g_bkt[EE];      // 16 MB: (key<<32)|edge_idx
__device__ unsigned char       g_meta[EE];     // 2 MB: head<<7 | lrank
__device__ unsigned            g_cnt[NB];
__device__ unsigned            g_start[NB];
__device__ unsigned            g_cur[NB];
__device__ unsigned            g_dcnt[NB];
__device__ unsigned            g_doff[NB];
__device__ unsigned            g_totalU;
__device__ int                 g_is32;

// ---------------- kernels ----------------------------------------------------

__global__ void k_zero() {
    int i = blockIdx.x * blockDim.x + threadIdx.x;
    if (i < NB) { g_cnt[i] = 0; g_cur[i] = 0; }
    if (i == 0) g_is32 = 0;
}

// dtype sniff: int64 values < 2^31 => every high word is 0. 2KB read, in-bounds either way.
__global__ void k_detect(const int2* __restrict__ ei) {
    if (ei[threadIdx.x].y != 0) atomicExch(&g_is32, 1);
}

__global__ void k_keys_hist(const void* __restrict__ eiv) {
    int e = blockIdx.x * blockDim.x + threadIdx.x;
    if (e >= EE) return;
    unsigned r, c;
    if (g_is32) {
        const int* ei = (const int*)eiv;
        r = (unsigned)ei[e]; c = (unsigned)ei[EE + e];
    } else {
        const long long* ei = (const long long*)eiv;
        r = (unsigned)ei[e]; c = (unsigned)ei[EE + e];
    }
    unsigned key = ((r >> 1) << 16) | (c >> 1);
    g_keys[e] = key;
    atomicAdd(&g_cnt[key >> 16], 1u);
}

// 64K exclusive scan: 1024 threads, 64 elems/thread, shuffle scan of partials
__global__ __launch_bounds__(1024) void k_scan64k(const unsigned* __restrict__ in,
                                                  unsigned* __restrict__ out,
                                                  unsigned* total) {
    __shared__ unsigned wsum[32];
    int tid = threadIdx.x;
    int lane = tid & 31, wid = tid >> 5;
    int base = tid * 64;
    unsigned sum = 0;
#pragma unroll 8
    for (int i = 0; i < 64; i++) sum += in[base + i];
    unsigned v = sum;
#pragma unroll
    for (int off = 1; off < 32; off <<= 1) {
        unsigned t = __shfl_up_sync(~0u, v, off);
        if (lane >= off) v += t;
    }
    if (lane == 31) wsum[wid] = v;
    __syncthreads();
    if (wid == 0) {
        unsigned w = wsum[lane];
#pragma unroll
        for (int off = 1; off < 32; off <<= 1) {
            unsigned t = __shfl_up_sync(~0u, w, off);
            if (lane >= off) w += t;
        }
        wsum[lane] = w;
    }
    __syncthreads();
    unsigned run = v - sum + (wid > 0 ? wsum[wid - 1] : 0u);  // exclusive prefix of chunk
#pragma unroll 8
    for (int i = 0; i < 64; i++) {
        unsigned x = in[base + i];
        out[base + i] = run;
        run += x;
    }
    if (tid == 1023 && total) *total = run;
}

__global__ void k_scatter() {
    int e = blockIdx.x * blockDim.x + threadIdx.x;
    if (e >= EE) return;
    unsigned key = g_keys[e];
    unsigned b = key >> 16;
    unsigned pos = g_start[b] + atomicAdd(&g_cur[b], 1u);
    g_bkt[pos] = ((unsigned long long)key << 32) | (unsigned)e;
}

// per-bucket bitonic sort (<=128 elems, 128 threads) + ballot head-flag scan
__global__ __launch_bounds__(MAXB) void k_sort() {
    __shared__ unsigned long long s[MAXB];
    __shared__ unsigned wtot[4];
    int b = blockIdx.x;
    unsigned tid = threadIdx.x;
    unsigned count = g_cnt[b];
    if (count == 0) { if (tid == 0) g_dcnt[b] = 0; return; }
    if (count > MAXB) count = MAXB;   // statistically impossible; safety
    unsigned start = g_start[b];
    unsigned m = 1; while (m < count) m <<= 1;

    s[tid] = (tid < count) ? g_bkt[start + tid] : 0xFFFFFFFFFFFFFFFFull;
    __syncthreads();
    for (unsigned k = 2; k <= m; k <<= 1) {
        for (unsigned j = k >> 1; j; j >>= 1) {
            unsigned ixj = tid ^ j;
            if (ixj > tid && ixj < m) {
                unsigned long long a = s[tid], c = s[ixj];
                bool asc = ((tid & k) == 0);
                if ((a > c) == asc) { s[tid] = c; s[ixj] = a; }
            }
            __syncthreads();
        }
    }
    unsigned key = (unsigned)(s[tid] >> 32);
    unsigned flag = 0;
    if (tid < count)
        flag = (tid == 0) || ((unsigned)(s[tid - 1] >> 32) != key);
    unsigned lane = tid & 31, wid = tid >> 5;
    unsigned bits = __ballot_sync(~0u, flag);
    unsigned pre = __popc(bits & ((1u << lane) - 1u));   // exclusive in-warp
    if (lane == 0) wtot[wid] = __popc(bits);
    __syncthreads();
    unsigned wbase = 0;
    for (unsigned w = 0; w < wid; w++) wbase += wtot[w];
    if (tid < count) {
        g_bkt[start + tid]  = s[tid];
        g_meta[start + tid] = (unsigned char)((flag << 7) | (wbase + pre));
    }
    if (tid == 0) g_dcnt[b] = wtot[0] + wtot[1] + wtot[2] + wtot[3];
}

// per-bucket run summation: heads gather+sum edge_attr, write attr + index rows
__global__ __launch_bounds__(MAXB) void k_runs(const float* __restrict__ ea,
                                               float* __restrict__ out) {
    int b = blockIdx.x;
    unsigned tid = threadIdx.x;
    unsigned count = g_cnt[b];
    if (count > MAXB) count = MAXB;
    if (tid >= count) return;
    unsigned start = g_start[b];
    unsigned char meta = g_meta[start + tid];
    if (!(meta & 0x80)) return;                    // not a run head
    unsigned rank = g_doff[b] + (meta & 0x7f);
    unsigned long long p = g_bkt[start + tid];
    unsigned key = (unsigned)(p >> 32);

    float4 a0 = {0,0,0,0}, a1 = {0,0,0,0}, a2 = {0,0,0,0}, a3 = {0,0,0,0};
    unsigned j = tid;
    while (true) {
        unsigned idx = (unsigned)p;
        const float4* row = (const float4*)(ea + (size_t)idx * DA);
        float4 r0 = row[0], r1 = row[1], r2 = row[2], r3 = row[3];
        a0.x += r0.x; a0.y += r0.y; a0.z += r0.z; a0.w += r0.w;
        a1.x += r1.x; a1.y += r1.y; a1.z += r1.z; a1.w += r1.w;
        a2.x += r2.x; a2.y += r2.y; a2.z += r2.z; a2.w += r2.w;
        a3.x += r3.x; a3.y += r3.y; a3.z += r3.z; a3.w += r3.w;
        j++;
        if (j >= count) break;
        p = g_bkt[start + j];
        if ((unsigned)(p >> 32) != key) break;
    }
    float4* eao = (float4*)(out + EA_OFF + (size_t)rank * DA);
    eao[0] = a0; eao[1] = a1; eao[2] = a2; eao[3] = a3;
    out[EI_OFF + rank]      = (float)(key >> 16);
    out[EI_OFF + EE + rank] = (float)(key & 0xFFFFu);
}

// padding: ranks >= U get (65536, 0) index and zero attr
__global__ void k_pad(float* __restrict__ out) {
    unsigned U = g_totalU;
    unsigned r = blockIdx.x * blockDim.x + threadIdx.x;
    if (r >= EE || r < U) return;
    out[EI_OFF + r]      = 65536.0f;
    out[EI_OFF + EE + r] = 0.0f;
    float4 z = {0,0,0,0};
    float4* eao = (float4*)(out + EA_OFF + (size_t)r * DA);
    eao[0] = z; eao[1] = z; eao[2] = z; eao[3] = z;
}

// 2x2 mean pool; float4 loads, float2 stores
__global__ void k_xpool(const float* __restrict__ x, float* __restrict__ out) {
    int t = blockIdx.x * blockDim.x + threadIdx.x;     // [0, NPOOL*FP/2)
    if (t >= NPOOL * (FP / 2)) return;
    int n  = t >> 7;           // pooled node
    int fq = t & 127;          // float4 index within row
    const float4* r0 = (const float4*)(x + (size_t)(2 * n) * FF)     + fq;
    const float4* r1 = (const float4*)(x + (size_t)(2 * n + 1) * FF) + fq;
    float4 a = *r0, b = *r1;
    float2 o;
    o.x = 0.25f * ((a.x + a.y) + (b.x + b.y));
    o.y = 0.25f * ((a.z + a.w) + (b.z + b.w));
    *(float2*)(out + X_OFF + (size_t)n * FP + 2 * fq) = o;
}

__global__ void k_batch(float* __restrict__ out) {
    int n = blockIdx.x * blockDim.x + threadIdx.x;
    if (n < NPOOL) out[BP_OFF + n] = (float)(n >> 10);
}

// ---------------- launch ------------------------------------------------------

extern "C" void kernel_launch(void* const* d_in, const int* in_sizes, int n_in,
                              void* d_out, int out_size) {
    const float* x  = (const float*)d_in[0];
    const float* ea = (const float*)d_in[1];
    const void*  ei = d_in[2];
    float* out = (float*)d_out;

    unsigned* d_cnt;  cudaGetSymbolAddress((void**)&d_cnt,  g_cnt);
    unsigned* d_start;cudaGetSymbolAddress((void**)&d_start,g_start);
    unsigned* d_dcnt; cudaGetSymbolAddress((void**)&d_dcnt, g_dcnt);
    unsigned* d_doff; cudaGetSymbolAddress((void**)&d_doff, g_doff);
    unsigned* d_tot;  cudaGetSymbolAddress((void**)&d_tot,  g_totalU);

    k_zero<<<(NB + 255) / 256, 256>>>();
    k_detect<<<1, 256>>>((const int2*)ei);
    k_keys_hist<<<(EE + 255) / 256, 256>>>(ei);
    k_scan64k<<<1, 1024>>>(d_cnt, d_start, nullptr);
    k_scatter<<<(EE + 255) / 256, 256>>>();
    k_sort<<<NB, MAXB>>>();
    k_scan64k<<<1, 1024>>>(d_dcnt, d_doff, d_tot);
    k_runs<<<NB, MAXB>>>(ea, out);
    k_pad<<<(EE + 255) / 256, 256>>>(out);
    k_xpool<<<(NPOOL * (FP / 2) + 255) / 256, 256>>>(x, out);
    k_batch<<<(NPOOL + 255) / 256, 256>>>(out);
}

// round 4
// speedup vs baseline: 1.3748x; 1.3748x over previous
#include <cuda_runtime.h>
#include <cuda_bf16.h>
#include <cstdint>

// Problem constants
#define NN      131072
#define FF      512
#define EE      2097152
#define DA      16
#define NPOOL   65536
#define FP      256
#define NB      65536       // buckets = pooled row (key >> 16)
#define MAXB    128         // max bucket size (Poisson mean 32; tail ~1e-15)
#define NSLOT   ((unsigned)NB * MAXB)   // 8M fixed slots

// Output layout (float elements, single concatenated array)
#define X_OFF   0ull
#define EI_OFF  16777216ull                              // 65536*256
#define EA_OFF  (EI_OFF + 2ull*EE)                       // 20971520
#define BP_OFF  (EA_OFF + (unsigned long long)EE*DA)     // 54525952

// ---------------- scratch ----------------------------------------------------
__device__ unsigned long long  g_bkt[NSLOT];   // 64 MB: (key<<32)|edge_idx, fixed slots
__device__ unsigned char       g_meta[NSLOT];  // 8 MB: head<<7 | lrank
__device__ unsigned            g_cnt[NB];
__device__ unsigned            g_dcnt[NB];
__device__ unsigned            g_doff[NB];
__device__ unsigned            g_part[256];
__device__ unsigned            g_partoff[256];
__device__ unsigned            g_totalU;
__device__ int                 g_is32;

// ---------------- kernels ----------------------------------------------------

__global__ void k_zero() {
    int i = blockIdx.x * blockDim.x + threadIdx.x;
    if (i < NB) g_cnt[i] = 0;
    if (i == 0) g_is32 = 0;
}

// dtype sniff: int64 values < 2^31 => every high word is 0. 2KB read, in-bounds either way.
__global__ void k_detect(const int2* __restrict__ ei) {
    if (ei[threadIdx.x].y != 0) atomicExch(&g_is32, 1);
}

// fused: compute key, count, scatter into fixed bucket slot
__global__ void k_scatter(const void* __restrict__ eiv) {
    int e = blockIdx.x * blockDim.x + threadIdx.x;
    if (e >= EE) return;
    unsigned r, c;
    if (g_is32) {
        const int* ei = (const int*)eiv;
        r = (unsigned)ei[e]; c = (unsigned)ei[EE + e];
    } else {
        const long long* ei = (const long long*)eiv;
        r = (unsigned)ei[e]; c = (unsigned)ei[EE + e];
    }
    unsigned key = ((r >> 1) << 16) | (c >> 1);
    unsigned b = key >> 16;
    unsigned pos = atomicAdd(&g_cnt[b], 1u);
    if (pos < MAXB)
        g_bkt[(size_t)b * MAXB + pos] = ((unsigned long long)key << 32) | (unsigned)e;
}

// per-bucket bitonic sort (<=128 elems, 128 threads) + ballot head-flag scan
__global__ __launch_bounds__(MAXB) void k_sort() {
    __shared__ unsigned long long s[MAXB];
    __shared__ unsigned wtot[4];
    int b = blockIdx.x;
    unsigned tid = threadIdx.x;
    unsigned count = g_cnt[b];
    if (count == 0) { if (tid == 0) g_dcnt[b] = 0; return; }
    if (count > MAXB) count = MAXB;   // statistically impossible; safety
    size_t start = (size_t)b * MAXB;
    unsigned m = 1; while (m < count) m <<= 1;

    s[tid] = (tid < count) ? g_bkt[start + tid] : 0xFFFFFFFFFFFFFFFFull;
    __syncthreads();
    for (unsigned k = 2; k <= m; k <<= 1) {
        for (unsigned j = k >> 1; j; j >>= 1) {
            unsigned ixj = tid ^ j;
            if (ixj > tid && ixj < m) {
                unsigned long long a = s[tid], c = s[ixj];
                bool asc = ((tid & k) == 0);
                if ((a > c) == asc) { s[tid] = c; s[ixj] = a; }
            }
            __syncthreads();
        }
    }
    unsigned key = (unsigned)(s[tid] >> 32);
    unsigned flag = 0;
    if (tid < count)
        flag = (tid == 0) || ((unsigned)(s[tid - 1] >> 32) != key);
    unsigned lane = tid & 31, wid = tid >> 5;
    unsigned bits = __ballot_sync(~0u, flag);
    unsigned pre = __popc(bits & ((1u << lane) - 1u));
    if (lane == 0) wtot[wid] = __popc(bits);
    __syncthreads();
    unsigned wbase = 0;
    for (unsigned w = 0; w < wid; w++) wbase += wtot[w];
    if (tid < count) {
        g_bkt[start + tid]  = s[tid];
        g_meta[start + tid] = (unsigned char)((flag << 7) | (wbase + pre));
    }
    if (tid == 0) g_dcnt[b] = wtot[0] + wtot[1] + wtot[2] + wtot[3];
}

// ---- 3-stage parallel 64K exclusive scan over g_dcnt -> g_doff --------------
// stage A: 256 blocks x 256 threads, block sums its 256-chunk
__global__ __launch_bounds__(256) void k_scanA() {
    __shared__ unsigned ws[8];
    int tid = threadIdx.x;
    unsigned v = g_dcnt[blockIdx.x * 256 + tid];
#pragma unroll
    for (int off = 16; off; off >>= 1) v += __shfl_down_sync(~0u, v, off);
    if ((tid & 31) == 0) ws[tid >> 5] = v;
    __syncthreads();
    if (tid == 0) {
        unsigned s = 0;
#pragma unroll
        for (int w = 0; w < 8; w++) s += ws[w];
        g_part[blockIdx.x] = s;
    }
}

// stage B: single block of 256: exclusive scan of partials
__global__ __launch_bounds__(256) void k_scanB() {
    __shared__ unsigned ws[8];
    int tid = threadIdx.x;
    int lane = tid & 31, wid = tid >> 5;
    unsigned x = g_part[tid];
    unsigned v = x;
#pragma unroll
    for (int off = 1; off < 32; off <<= 1) {
        unsigned t = __shfl_up_sync(~0u, v, off);
        if (lane >= off) v += t;
    }
    if (lane == 31) ws[wid] = v;
    __syncthreads();
    if (wid == 0 && lane < 8) {
        unsigned w = ws[lane];
#pragma unroll
        for (int off = 1; off < 8; off <<= 1) {
            unsigned t = __shfl_up_sync(0xffu, w, off);
            if (lane >= off) w += t;
        }
        ws[lane] = w;
    }
    __syncthreads();
    unsigned excl = v - x + (wid > 0 ? ws[wid - 1] : 0u);
    g_partoff[tid] = excl;
    if (tid == 255) g_totalU = excl + x;
}

// stage C: 256 blocks x 256 threads: block-local exclusive scan + partoff
__global__ __launch_bounds__(256) void k_scanC() {
    __shared__ unsigned ws[8];
    int tid = threadIdx.x;
    int lane = tid & 31, wid = tid >> 5;
    int i = blockIdx.x * 256 + tid;
    unsigned x = g_dcnt[i];
    unsigned v = x;
#pragma unroll
    for (int off = 1; off < 32; off <<= 1) {
        unsigned t = __shfl_up_sync(~0u, v, off);
        if (lane >= off) v += t;
    }
    if (lane == 31) ws[wid] = v;
    __syncthreads();
    if (wid == 0 && lane < 8) {
        unsigned w = ws[lane];
#pragma unroll
        for (int off = 1; off < 8; off <<= 1) {
            unsigned t = __shfl_up_sync(0xffu, w, off);
            if (lane >= off) w += t;
        }
        ws[lane] = w;
    }
    __syncthreads();
    g_doff[i] = g_partoff[blockIdx.x] + v - x + (wid > 0 ? ws[wid - 1] : 0u);
}

// per-bucket run summation: heads gather+sum edge_attr, write attr + index rows
__global__ __launch_bounds__(MAXB) void k_runs(const float* __restrict__ ea,
                                               float* __restrict__ out) {
    int b = blockIdx.x;
    unsigned tid = threadIdx.x;
    unsigned count = g_cnt[b];
    if (count > MAXB) count = MAXB;
    if (tid >= count) return;
    size_t start = (size_t)b * MAXB;
    unsigned char meta = g_meta[start + tid];
    if (!(meta & 0x80)) return;                    // not a run head
    unsigned rank = g_doff[b] + (meta & 0x7f);
    unsigned long long p = g_bkt[start + tid];
    unsigned key = (unsigned)(p >> 32);

    float4 a0 = {0,0,0,0}, a1 = {0,0,0,0}, a2 = {0,0,0,0}, a3 = {0,0,0,0};
    unsigned j = tid;
    while (true) {
        unsigned idx = (unsigned)p;
        const float4* row = (const float4*)(ea + (size_t)idx * DA);
        float4 r0 = row[0], r1 = row[1], r2 = row[2], r3 = row[3];
        a0.x += r0.x; a0.y += r0.y; a0.z += r0.z; a0.w += r0.w;
        a1.x += r1.x; a1.y += r1.y; a1.z += r1.z; a1.w += r1.w;
        a2.x += r2.x; a2.y += r2.y; a2.z += r2.z; a2.w += r2.w;
        a3.x += r3.x; a3.y += r3.y; a3.z += r3.z; a3.w += r3.w;
        j++;
        if (j >= count) break;
        p = g_bkt[start + j];
        if ((unsigned)(p >> 32) != key) break;
    }
    float4* eao = (float4*)(out + EA_OFF + (size_t)rank * DA);
    eao[0] = a0; eao[1] = a1; eao[2] = a2; eao[3] = a3;
    out[EI_OFF + rank]      = (float)(key >> 16);
    out[EI_OFF + EE + rank] = (float)(key & 0xFFFFu);
}

// padding: ranks >= U get (65536, 0) index and zero attr (~500 rows)
__global__ void k_pad(float* __restrict__ out) {
    unsigned U = g_totalU;
    unsigned r = blockIdx.x * blockDim.x + threadIdx.x;
    if (r >= EE || r < U) return;
    out[EI_OFF + r]      = 65536.0f;
    out[EI_OFF + EE + r] = 0.0f;
    float4 z = {0,0,0,0};
    float4* eao = (float4*)(out + EA_OFF + (size_t)r * DA);
    eao[0] = z; eao[1] = z; eao[2] = z; eao[3] = z;
}

// 2x2 mean pool; float4 loads, float2 stores
__global__ void k_xpool(const float* __restrict__ x, float* __restrict__ out) {
    int t = blockIdx.x * blockDim.x + threadIdx.x;
    if (t >= NPOOL * (FP / 2)) return;
    int n  = t >> 7;
    int fq = t & 127;
    const float4* r0 = (const float4*)(x + (size_t)(2 * n) * FF)     + fq;
    const float4* r1 = (const float4*)(x + (size_t)(2 * n + 1) * FF) + fq;
    float4 a = *r0, b = *r1;
    float2 o;
    o.x = 0.25f * ((a.x + a.y) + (b.x + b.y));
    o.y = 0.25f * ((a.z + a.w) + (b.z + b.w));
    *(float2*)(out + X_OFF + (size_t)n * FP + 2 * fq) = o;
}

__global__ void k_batch(float* __restrict__ out) {
    int n = blockIdx.x * blockDim.x + threadIdx.x;
    if (n < NPOOL) out[BP_OFF + n] = (float)(n >> 10);
}

// ---------------- launch ------------------------------------------------------

extern "C" void kernel_launch(void* const* d_in, const int* in_sizes, int n_in,
                              void* d_out, int out_size) {
    const float* x  = (const float*)d_in[0];
    const float* ea = (const float*)d_in[1];
    const void*  ei = d_in[2];
    float* out = (float*)d_out;

    k_zero<<<(NB + 255) / 256, 256>>>();
    k_detect<<<1, 256>>>((const int2*)ei);
    k_scatter<<<(EE + 255) / 256, 256>>>(ei);
    k_sort<<<NB, MAXB>>>();
    k_scanA<<<256, 256>>>();
    k_scanB<<<1, 256>>>();
    k_scanC<<<256, 256>>>();
    k_runs<<<NB, MAXB>>>(ea, out);
    k_pad<<<(EE + 255) / 256, 256>>>(out);
    k_xpool<<<(NPOOL * (FP / 2) + 255) / 256, 256>>>(x, out);
    k_batch<<<(NPOOL + 255) / 256, 256>>>(out);
}

// round 5
// speedup vs baseline: 2.2604x; 1.6441x over previous
#include <cuda_runtime.h>
#include <cuda_bf16.h>
#include <cstdint>

// Problem constants
#define NN      131072
#define FF      512
#define EE      2097152
#define DA      16
#define NPOOL   65536
#define FP      256
#define NB      65536       // buckets = pooled row (key >> 16)
#define MAXB    128         // max bucket size (Poisson mean 32)
#define NSLOT   ((unsigned)NB * MAXB)
#define SWARPS  8           // buckets per sort block

// Output layout (float elements, single concatenated array)
#define X_OFF   0ull
#define EI_OFF  16777216ull
#define EA_OFF  (EI_OFF + 2ull*EE)
#define BP_OFF  (EA_OFF + (unsigned long long)EE*DA)

// ---------------- scratch ----------------------------------------------------
__device__ unsigned long long  g_bkt[NSLOT];   // 64 MB fixed slots
__device__ unsigned char       g_meta[NSLOT];  // head<<7 | lrank
__device__ unsigned            g_cnt[NB];
__device__ unsigned            g_dcnt[NB];
__device__ unsigned            g_doff[NB];
__device__ unsigned            g_part[256];
__device__ unsigned            g_partoff[256];
__device__ unsigned            g_totalU;
__device__ int                 g_is32;

// ---------------- kernels ----------------------------------------------------

__global__ void k_zero() {
    int i = blockIdx.x * blockDim.x + threadIdx.x;
    if (i < NB) g_cnt[i] = 0;
    if (i == 0) g_is32 = 0;
}

__global__ void k_detect(const int2* __restrict__ ei) {
    if (ei[threadIdx.x].y != 0) atomicExch(&g_is32, 1);
}

// fused: key, count, scatter into fixed bucket slot
__global__ void k_scatter(const void* __restrict__ eiv) {
    int e = blockIdx.x * blockDim.x + threadIdx.x;
    if (e >= EE) return;
    unsigned r, c;
    if (g_is32) {
        const int* ei = (const int*)eiv;
        r = (unsigned)ei[e]; c = (unsigned)ei[EE + e];
    } else {
        const long long* ei = (const long long*)eiv;
        r = (unsigned)ei[e]; c = (unsigned)ei[EE + e];
    }
    unsigned key = ((r >> 1) << 16) | (c >> 1);
    unsigned b = key >> 16;
    unsigned pos = atomicAdd(&g_cnt[b], 1u);
    if (pos < MAXB)
        g_bkt[(size_t)b * MAXB + pos] = ((unsigned long long)key << 32) | (unsigned)e;
}

// ---- warp-level bitonic sort of NR*32 64-bit items, zero barriers -----------
template<int NR>
__device__ __forceinline__ void warp_bitonic(unsigned long long (&v)[NR], unsigned lane) {
    const unsigned N = NR * 32;
#pragma unroll
    for (unsigned k = 2; k <= N; k <<= 1) {
#pragma unroll
        for (unsigned j = N >> 1; j > 0; j >>= 1) {
            if (j >= k) continue;   // compile-time pruned
            if (j >= 32) {
                unsigned rj = j >> 5;
#pragma unroll
                for (int r = 0; r < NR; r++) {
                    if ((r & (int)rj) == 0 && (r ^ (int)rj) < NR) {
                        int r2 = r ^ (int)rj;
                        unsigned ia = r * 32 + lane;
                        bool up = ((ia & k) == 0);
                        unsigned long long a = v[r], b = v[r2];
                        if ((a > b) == up) { v[r] = b; v[r2] = a; }
                    }
                }
            } else {
#pragma unroll
                for (int r = 0; r < NR; r++) {
                    unsigned i = r * 32 + lane;
                    unsigned long long x = v[r];
                    unsigned long long y = __shfl_xor_sync(~0u, x, j);
                    bool up = ((i & k) == 0);
                    bool keepmin = (((lane & j) == 0) == up);
                    v[r] = keepmin ? (x < y ? x : y) : (x > y ? x : y);
                }
            }
        }
    }
}

template<int NR>
__device__ __forceinline__ void sort_bucket(unsigned b, unsigned count, unsigned lane) {
    size_t start = (size_t)b * MAXB;
    unsigned long long v[NR];
#pragma unroll
    for (int r = 0; r < NR; r++) {
        unsigned i = r * 32 + lane;
        v[r] = (i < count) ? g_bkt[start + i] : 0xFFFFFFFFFFFFFFFFull;
    }
    warp_bitonic<NR>(v, lane);

    unsigned mask[NR];
    unsigned long long prev_last = 0;
#pragma unroll
    for (int r = 0; r < NR; r++) {
        unsigned long long p = __shfl_up_sync(~0u, v[r], 1);
        unsigned long long last = __shfl_sync(~0u, v[r], 31);
        if (lane == 0) p = prev_last;
        unsigned i = r * 32 + lane;
        bool head = (i < count) &&
                    ((i == 0) || ((unsigned)(p >> 32) != (unsigned)(v[r] >> 32)));
        mask[r] = __ballot_sync(~0u, head);
        prev_last = last;
    }
    unsigned base = 0;
#pragma unroll
    for (int r = 0; r < NR; r++) {
        unsigned i = r * 32 + lane;
        if (i < count) {
            unsigned head = (mask[r] >> lane) & 1u;
            unsigned lr = base + __popc(mask[r] & ((1u << lane) - 1u));
            g_bkt[start + i]  = v[r];
            g_meta[start + i] = (unsigned char)((head << 7) | lr);
        }
        base += __popc(mask[r]);
    }
    if (lane == 0) g_dcnt[b] = base;
}

__global__ __launch_bounds__(32 * SWARPS) void k_sort() {
    unsigned lane = threadIdx.x & 31;
    unsigned b = blockIdx.x * SWARPS + (threadIdx.x >> 5);
    unsigned count = g_cnt[b];
    if (count == 0) { if (lane == 0) g_dcnt[b] = 0; return; }
    if (count > MAXB) count = MAXB;   // statistically impossible; safety
    if (count <= 64) sort_bucket<2>(b, count, lane);
    else             sort_bucket<4>(b, count, lane);
}

// ---- 3-stage parallel 64K exclusive scan over g_dcnt -> g_doff --------------
__global__ __launch_bounds__(256) void k_scanA() {
    __shared__ unsigned ws[8];
    int tid = threadIdx.x;
    unsigned v = g_dcnt[blockIdx.x * 256 + tid];
#pragma unroll
    for (int off = 16; off; off >>= 1) v += __shfl_down_sync(~0u, v, off);
    if ((tid & 31) == 0) ws[tid >> 5] = v;
    __syncthreads();
    if (tid == 0) {
        unsigned s = 0;
#pragma unroll
        for (int w = 0; w < 8; w++) s += ws[w];
        g_part[blockIdx.x] = s;
    }
}

__global__ __launch_bounds__(256) void k_scanB() {
    __shared__ unsigned ws[8];
    int tid = threadIdx.x;
    int lane = tid & 31, wid = tid >> 5;
    unsigned x = g_part[tid];
    unsigned v = x;
#pragma unroll
    for (int off = 1; off < 32; off <<= 1) {
        unsigned t = __shfl_up_sync(~0u, v, off);
        if (lane >= off) v += t;
    }
    if (lane == 31) ws[wid] = v;
    __syncthreads();
    if (wid == 0 && lane < 8) {
        unsigned w = ws[lane];
#pragma unroll
        for (int off = 1; off < 8; off <<= 1) {
            unsigned t = __shfl_up_sync(0xffu, w, off);
            if (lane >= off) w += t;
        }
        ws[lane] = w;
    }
    __syncthreads();
    unsigned excl = v - x + (wid > 0 ? ws[wid - 1] : 0u);
    g_partoff[tid] = excl;
    if (tid == 255) g_totalU = excl + x;
}

__global__ __launch_bounds__(256) void k_scanC() {
    __shared__ unsigned ws[8];
    int tid = threadIdx.x;
    int lane = tid & 31, wid = tid >> 5;
    int i = blockIdx.x * 256 + tid;
    unsigned x = g_dcnt[i];
    unsigned v = x;
#pragma unroll
    for (int off = 1; off < 32; off <<= 1) {
        unsigned t = __shfl_up_sync(~0u, v, off);
        if (lane >= off) v += t;
    }
    if (lane == 31) ws[wid] = v;
    __syncthreads();
    if (wid == 0 && lane < 8) {
        unsigned w = ws[lane];
#pragma unroll
        for (int off = 1; off < 8; off <<= 1) {
            unsigned t = __shfl_up_sync(0xffu, w, off);
            if (lane >= off) w += t;
        }
        ws[lane] = w;
    }
    __syncthreads();
    g_doff[i] = g_partoff[blockIdx.x] + v - x + (wid > 0 ? ws[wid - 1] : 0u);
}

// per-bucket run summation
__global__ __launch_bounds__(MAXB) void k_runs(const float* __restrict__ ea,
                                               float* __restrict__ out) {
    int b = blockIdx.x;
    unsigned tid = threadIdx.x;
    unsigned count = g_cnt[b];
    if (count > MAXB) count = MAXB;
    if (tid >= count) return;
    size_t start = (size_t)b * MAXB;
    unsigned char meta = g_meta[start + tid];
    if (!(meta & 0x80)) return;
    unsigned rank = g_doff[b] + (meta & 0x7f);
    unsigned long long p = g_bkt[start + tid];
    unsigned key = (unsigned)(p >> 32);

    float4 a0 = {0,0,0,0}, a1 = {0,0,0,0}, a2 = {0,0,0,0}, a3 = {0,0,0,0};
    unsigned j = tid;
    while (true) {
        unsigned idx = (unsigned)p;
        const float4* row = (const float4*)(ea + (size_t)idx * DA);
        float4 r0 = row[0], r1 = row[1], r2 = row[2], r3 = row[3];
        a0.x += r0.x; a0.y += r0.y; a0.z += r0.z; a0.w += r0.w;
        a1.x += r1.x; a1.y += r1.y; a1.z += r1.z; a1.w += r1.w;
        a2.x += r2.x; a2.y += r2.y; a2.z += r2.z; a2.w += r2.w;
        a3.x += r3.x; a3.y += r3.y; a3.z += r3.z; a3.w += r3.w;
        j++;
        if (j >= count) break;
        p = g_bkt[start + j];
        if ((unsigned)(p >> 32) != key) break;
    }
    float4* eao = (float4*)(out + EA_OFF + (size_t)rank * DA);
    eao[0] = a0; eao[1] = a1; eao[2] = a2; eao[3] = a3;
    out[EI_OFF + rank]      = (float)(key >> 16);
    out[EI_OFF + EE + rank] = (float)(key & 0xFFFFu);
}

// padding: ranks >= U get (65536, 0) index and zero attr
__global__ void k_pad(float* __restrict__ out) {
    unsigned U = g_totalU;
    unsigned r = blockIdx.x * blockDim.x + threadIdx.x;
    if (r >= EE || r < U) return;
    out[EI_OFF + r]      = 65536.0f;
    out[EI_OFF + EE + r] = 0.0f;
    float4 z = {0,0,0,0};
    float4* eao = (float4*)(out + EA_OFF + (size_t)r * DA);
    eao[0] = z; eao[1] = z; eao[2] = z; eao[3] = z;
}

// 2x2 mean pool; float4 loads, float2 stores
__global__ void k_xpool(const float* __restrict__ x, float* __restrict__ out) {
    int t = blockIdx.x * blockDim.x + threadIdx.x;
    if (t >= NPOOL * (FP / 2)) return;
    int n  = t >> 7;
    int fq = t & 127;
    const float4* r0 = (const float4*)(x + (size_t)(2 * n) * FF)     + fq;
    const float4* r1 = (const float4*)(x + (size_t)(2 * n + 1) * FF) + fq;
    float4 a = *r0, b = *r1;
    float2 o;
    o.x = 0.25f * ((a.x + a.y) + (b.x + b.y));
    o.y = 0.25f * ((a.z + a.w) + (b.z + b.w));
    *(float2*)(out + X_OFF + (size_t)n * FP + 2 * fq) = o;
}

__global__ void k_batch(float* __restrict__ out) {
    int n = blockIdx.x * blockDim.x + threadIdx.x;
    if (n < NPOOL) out[BP_OFF + n] = (float)(n >> 10);
}

// ---------------- launch ------------------------------------------------------

extern "C" void kernel_launch(void* const* d_in, const int* in_sizes, int n_in,
                              void* d_out, int out_size) {
    const float* x  = (const float*)d_in[0];
    const float* ea = (const float*)d_in[1];
    const void*  ei = d_in[2];
    float* out = (float*)d_out;

    k_zero<<<(NB + 255) / 256, 256>>>();
    k_detect<<<1, 256>>>((const int2*)ei);
    k_scatter<<<(EE + 255) / 256, 256>>>(ei);
    k_sort<<<NB / SWARPS, 32 * SWARPS>>>();
    k_scanA<<<256, 256>>>();
    k_scanB<<<1, 256>>>();
    k_scanC<<<256, 256>>>();
    k_runs<<<NB, MAXB>>>(ea, out);
    k_pad<<<(EE + 255) / 256, 256>>>(out);
    k_xpool<<<(NPOOL * (FP / 2) + 255) / 256, 256>>>(x, out);
    k_batch<<<(NPOOL + 255) / 256, 256>>>(out);
}

// round 6
// speedup vs baseline: 2.8070x; 1.2418x over previous
#include <cuda_runtime.h>
#include <cuda_bf16.h>
#include <cstdint>

// Problem constants
#define NN      131072
#define FF      512
#define EE      2097152
#define DA      16
#define NPOOL   65536
#define FP      256
#define NB      65536       // buckets = pooled row (key >> 16)
#define MAXB    128         // max bucket size (Poisson mean 32)
#define NSLOT   ((unsigned)NB * MAXB)

// Output layout (float elements, single concatenated array)
#define X_OFF   0ull
#define EI_OFF  16777216ull
#define EA_OFF  (EI_OFF + 2ull*EE)
#define BP_OFF  (EA_OFF + (unsigned long long)EE*DA)

// ---------------- scratch ----------------------------------------------------
__device__ unsigned long long  g_bkt[NSLOT];   // 64 MB fixed slots: (key<<32)|edge
__device__ unsigned short      g_ms[NSLOT];    // 16 MB: head<<15 | lrank<<8 | slot
__device__ unsigned            g_cnt[NB];
__device__ unsigned            g_dcnt[NB];
__device__ unsigned            g_doff[NB];
__device__ unsigned            g_part[256];
__device__ unsigned            g_partoff[256];
__device__ unsigned            g_totalU;
__device__ int                 g_is32;

// ---------------- kernels ----------------------------------------------------

// dtype sniff, single warp: int64 values < 2^31 => every high word is 0.
__global__ void k_detect(const int2* __restrict__ ei) {
    unsigned lane = threadIdx.x;
    bool nz = false;
#pragma unroll
    for (int k = 0; k < 8; k++) nz |= (ei[lane * 8 + k].y != 0);
    unsigned m = __ballot_sync(~0u, nz);
    if (lane == 0) g_is32 = (m != 0) ? 1 : 0;
}

// fused: key, count, scatter into fixed bucket slot
__global__ void k_scatter(const void* __restrict__ eiv) {
    int e = blockIdx.x * blockDim.x + threadIdx.x;
    if (e >= EE) return;
    unsigned r, c;
    if (g_is32) {
        const int* ei = (const int*)eiv;
        r = (unsigned)ei[e]; c = (unsigned)ei[EE + e];
    } else {
        const long long* ei = (const long long*)eiv;
        r = (unsigned)ei[e]; c = (unsigned)ei[EE + e];
    }
    unsigned key = ((r >> 1) << 16) | (c >> 1);
    unsigned b = key >> 16;
    unsigned pos = atomicAdd(&g_cnt[b], 1u);
    if (pos < MAXB)
        g_bkt[(size_t)b * MAXB + pos] = ((unsigned long long)key << 32) | (unsigned)e;
}

// ---- warp-level bitonic sort on 32-bit items, zero barriers -----------------
template<int NR>
__device__ __forceinline__ void warp_bitonic32(unsigned (&v)[NR], unsigned lane) {
    const unsigned N = NR * 32;
#pragma unroll
    for (unsigned k = 2; k <= N; k <<= 1) {
#pragma unroll
        for (unsigned j = N >> 1; j > 0; j >>= 1) {
            if (j >= k) continue;   // compile-time pruned
            if (j >= 32) {
                unsigned rj = j >> 5;
#pragma unroll
                for (int r = 0; r < NR; r++) {
                    if ((r & (int)rj) == 0 && (r ^ (int)rj) < NR) {
                        int r2 = r ^ (int)rj;
                        unsigned ia = r * 32 + lane;
                        bool up = ((ia & k) == 0);
                        unsigned a = v[r], b = v[r2];
                        if ((a > b) == up) { v[r] = b; v[r2] = a; }
                    }
                }
            } else {
#pragma unroll
                for (int r = 0; r < NR; r++) {
                    unsigned i = r * 32 + lane;
                    unsigned x = v[r];
                    unsigned y = __shfl_xor_sync(~0u, x, j);
                    bool up = ((i & k) == 0);
                    bool keepmin = (((lane & j) == 0) == up);
                    v[r] = keepmin ? (x < y ? x : y) : (x > y ? x : y);
                }
            }
        }
    }
}

template<int NR>
__device__ __forceinline__ void sort_bucket(unsigned b, unsigned count, unsigned lane) {
    size_t start = (size_t)b * MAXB;
    unsigned v[NR];
#pragma unroll
    for (int r = 0; r < NR; r++) {
        unsigned i = r * 32 + lane;
        if (i < count) {
            unsigned key = (unsigned)(g_bkt[start + i] >> 32);
            v[r] = ((key & 0xFFFFu) << 7) | i;     // col<<7 | slot
        } else v[r] = 0xFFFFFFFFu;
    }
    warp_bitonic32<NR>(v, lane);

    unsigned mask[NR];
    unsigned prev_last = 0xFFFFFFFFu;
#pragma unroll
    for (int r = 0; r < NR; r++) {
        unsigned p = __shfl_up_sync(~0u, v[r], 1);
        unsigned last = __shfl_sync(~0u, v[r], 31);
        if (lane == 0) p = prev_last;
        unsigned i = r * 32 + lane;
        bool head = (i < count) && ((i == 0) || ((p >> 7) != (v[r] >> 7)));
        mask[r] = __ballot_sync(~0u, head);
        prev_last = last;
    }
    unsigned base = 0;
#pragma unroll
    for (int r = 0; r < NR; r++) {
        unsigned i = r * 32 + lane;
        if (i < count) {
            unsigned head = (mask[r] >> lane) & 1u;
            unsigned lr = base + __popc(mask[r] & ((1u << lane) - 1u));
            g_ms[start + i] = (unsigned short)((head << 15) | (lr << 8) | (v[r] & 0x7Fu));
        }
        base += __popc(mask[r]);
    }
    if (lane == 0) g_dcnt[b] = base;
}

// fat kernel: 1-in-5 blocks sort (8 buckets/block), 4-in-5 blocks do xpool
#define SORTXP_GRID (8192 * 5)
__global__ __launch_bounds__(256) void k_sort_xpool(const float* __restrict__ x,
                                                    float* __restrict__ out) {
    unsigned bid = blockIdx.x;
    if (bid % 5 == 0) {
        unsigned sid = bid / 5;
        unsigned lane = threadIdx.x & 31;
        unsigned b = sid * 8 + (threadIdx.x >> 5);
        unsigned count = g_cnt[b];
        if (count == 0) { if (lane == 0) g_dcnt[b] = 0; return; }
        if (count > MAXB) count = MAXB;   // statistically impossible; safety
        if (count <= 64) sort_bucket<2>(b, count, lane);
        else             sort_bucket<4>(b, count, lane);
    } else {
        unsigned xid = bid - bid / 5 - 1;          // 0 .. 32767
        unsigned t = xid * 256 + threadIdx.x;
        if (t >= NPOOL * (FP / 2)) return;
        unsigned n  = t >> 7;
        unsigned fq = t & 127;
        const float4* r0 = (const float4*)(x + (size_t)(2 * n) * FF)     + fq;
        const float4* r1 = (const float4*)(x + (size_t)(2 * n + 1) * FF) + fq;
        float4 a = *r0, b = *r1;
        float2 o;
        o.x = 0.25f * ((a.x + a.y) + (b.x + b.y));
        o.y = 0.25f * ((a.z + a.w) + (b.z + b.w));
        *(float2*)(out + X_OFF + (size_t)n * FP + 2 * fq) = o;
    }
}

// ---- 3-stage parallel 64K exclusive scan over g_dcnt -> g_doff --------------
__global__ __launch_bounds__(256) void k_scanA() {
    __shared__ unsigned ws[8];
    int tid = threadIdx.x;
    unsigned v = g_dcnt[blockIdx.x * 256 + tid];
#pragma unroll
    for (int off = 16; off; off >>= 1) v += __shfl_down_sync(~0u, v, off);
    if ((tid & 31) == 0) ws[tid >> 5] = v;
    __syncthreads();
    if (tid == 0) {
        unsigned s = 0;
#pragma unroll
        for (int w = 0; w < 8; w++) s += ws[w];
        g_part[blockIdx.x] = s;
    }
}

__global__ __launch_bounds__(256) void k_scanB() {
    __shared__ unsigned ws[8];
    int tid = threadIdx.x;
    int lane = tid & 31, wid = tid >> 5;
    unsigned x = g_part[tid];
    unsigned v = x;
#pragma unroll
    for (int off = 1; off < 32; off <<= 1) {
        unsigned t = __shfl_up_sync(~0u, v, off);
        if (lane >= off) v += t;
    }
    if (lane == 31) ws[wid] = v;
    __syncthreads();
    if (wid == 0 && lane < 8) {
        unsigned w = ws[lane];
#pragma unroll
        for (int off = 1; off < 8; off <<= 1) {
            unsigned t = __shfl_up_sync(0xffu, w, off);
            if (lane >= off) w += t;
        }
        ws[lane] = w;
    }
    __syncthreads();
    unsigned excl = v - x + (wid > 0 ? ws[wid - 1] : 0u);
    g_partoff[tid] = excl;
    if (tid == 255) g_totalU = excl + x;
}

__global__ __launch_bounds__(256) void k_scanC() {
    __shared__ unsigned ws[8];
    int tid = threadIdx.x;
    int lane = tid & 31, wid = tid >> 5;
    int i = blockIdx.x * 256 + tid;
    unsigned x = g_dcnt[i];
    unsigned v = x;
#pragma unroll
    for (int off = 1; off < 32; off <<= 1) {
        unsigned t = __shfl_up_sync(~0u, v, off);
        if (lane >= off) v += t;
    }
    if (lane == 31) ws[wid] = v;
    __syncthreads();
    if (wid == 0 && lane < 8) {
        unsigned w = ws[lane];
#pragma unroll
        for (int off = 1; off < 8; off <<= 1) {
            unsigned t = __shfl_up_sync(0xffu, w, off);
            if (lane >= off) w += t;
        }
        ws[lane] = w;
    }
    __syncthreads();
    g_doff[i] = g_partoff[blockIdx.x] + v - x + (wid > 0 ? ws[wid - 1] : 0u);
}

// fat tail: runs (warp/bucket) + pad + batch
#define TAIL_GRID (8192 + 8192 + 256)
__global__ __launch_bounds__(256) void k_tail(const float* __restrict__ ea,
                                              float* __restrict__ out) {
    unsigned bid = blockIdx.x;
    if (bid < 8192) {
        unsigned lane = threadIdx.x & 31;
        unsigned b = bid * 8 + (threadIdx.x >> 5);
        unsigned count = g_cnt[b];
        if (count > MAXB) count = MAXB;
        if (count == 0) return;
        size_t start = (size_t)b * MAXB;
        unsigned doff = g_doff[b];
        for (unsigned i0 = 0; i0 < count; i0 += 32) {
            unsigned i = i0 + lane;
            if (i >= count) break;
            unsigned ms = g_ms[start + i];
            if (!(ms & 0x8000u)) continue;         // not a run head
            unsigned rank = doff + ((ms >> 8) & 0x7Fu);
            unsigned long long p = g_bkt[start + (ms & 0x7Fu)];
            unsigned key = (unsigned)(p >> 32);
            const float4* row = (const float4*)(ea + (size_t)(unsigned)p * DA);
            float4 a0 = row[0], a1 = row[1], a2 = row[2], a3 = row[3];
            unsigned j = i + 1;
            while (j < count) {
                unsigned ms2 = g_ms[start + j];
                if (ms2 & 0x8000u) break;
                unsigned long long p2 = g_bkt[start + (ms2 & 0x7Fu)];
                const float4* r2 = (const float4*)(ea + (size_t)(unsigned)p2 * DA);
                float4 b0 = r2[0], b1 = r2[1], b2 = r2[2], b3 = r2[3];
                a0.x += b0.x; a0.y += b0.y; a0.z += b0.z; a0.w += b0.w;
                a1.x += b1.x; a1.y += b1.y; a1.z += b1.z; a1.w += b1.w;
                a2.x += b2.x; a2.y += b2.y; a2.z += b2.z; a2.w += b2.w;
                a3.x += b3.x; a3.y += b3.y; a3.z += b3.z; a3.w += b3.w;
                j++;
            }
            float4* eao = (float4*)(out + EA_OFF + (size_t)rank * DA);
            eao[0] = a0; eao[1] = a1; eao[2] = a2; eao[3] = a3;
            out[EI_OFF + rank]      = (float)(key >> 16);
            out[EI_OFF + EE + rank] = (float)(key & 0xFFFFu);
        }
    } else if (bid < 16384) {
        unsigned U = g_totalU;
        unsigned r = (bid - 8192) * 256 + threadIdx.x;
        if (r >= EE || r < U) return;
        out[EI_OFF + r]      = 65536.0f;
        out[EI_OFF + EE + r] = 0.0f;
        float4 z = {0, 0, 0, 0};
        float4* eao = (float4*)(out + EA_OFF + (size_t)r * DA);
        eao[0] = z; eao[1] = z; eao[2] = z; eao[3] = z;
    } else {
        unsigned n = (bid - 16384) * 256 + threadIdx.x;
        if (n < NPOOL) out[BP_OFF + n] = (float)(n >> 10);
    }
}

// ---------------- launch ------------------------------------------------------

extern "C" void kernel_launch(void* const* d_in, const int* in_sizes, int n_in,
                              void* d_out, int out_size) {
    const float* x  = (const float*)d_in[0];
    const float* ea = (const float*)d_in[1];
    const void*  ei = d_in[2];
    float* out = (float*)d_out;

    unsigned* d_cnt; cudaGetSymbolAddress((void**)&d_cnt, g_cnt);
    cudaMemsetAsync(d_cnt, 0, NB * sizeof(unsigned));
    k_detect<<<1, 32>>>((const int2*)ei);
    k_scatter<<<(EE + 255) / 256, 256>>>(ei);
    k_sort_xpool<<<SORTXP_GRID, 256>>>(x, out);
    k_scanA<<<256, 256>>>();
    k_scanB<<<1, 256>>>();
    k_scanC<<<256, 256>>>();
    k_tail<<<TAIL_GRID, 256>>>(ea, out);
}

// round 7
// speedup vs baseline: 2.9302x; 1.0439x over previous
#include <cuda_runtime.h>
#include <cuda_bf16.h>
#include <cstdint>

// Problem constants
#define NN      131072
#define FF      512
#define EE      2097152
#define DA      16
#define NPOOL   65536
#define FP      256
#define NB      65536       // buckets = pooled row (key >> 16)
#define MAXB    128         // max bucket size (Poisson mean 32)
#define NSLOT   ((unsigned)NB * MAXB)

// Output layout (float elements, single concatenated array)
#define X_OFF   0ull
#define EI_OFF  16777216ull
#define EA_OFF  (EI_OFF + 2ull*EE)
#define BP_OFF  (EA_OFF + (unsigned long long)EE*DA)

// ---------------- scratch ----------------------------------------------------
__device__ unsigned long long  g_bkt[NSLOT];   // 64 MB fixed slots: (key<<32)|edge
__device__ unsigned short      g_ms[NSLOT];    // 16 MB: head<<15 | lrank<<8 | slot
__device__ unsigned            g_cnt[NB];
__device__ unsigned            g_dcnt[NB];
__device__ unsigned            g_doff[NB];
__device__ unsigned            g_part[256];
__device__ unsigned            g_partoff[256];
__device__ unsigned            g_totalU;
__device__ int                 g_is32;

// ---------------- helpers ------------------------------------------------------

__device__ __forceinline__ void xpool_chunk(unsigned t, const float* __restrict__ x,
                                            float* __restrict__ out) {
    if (t >= NPOOL * (FP / 2)) return;
    unsigned n  = t >> 7;
    unsigned fq = t & 127;
    const float4* r0 = (const float4*)(x + (size_t)(2 * n) * FF)     + fq;
    const float4* r1 = (const float4*)(x + (size_t)(2 * n + 1) * FF) + fq;
    float4 a = *r0, b = *r1;
    float2 o;
    o.x = 0.25f * ((a.x + a.y) + (b.x + b.y));
    o.y = 0.25f * ((a.z + a.w) + (b.z + b.w));
    *(float2*)(out + X_OFF + (size_t)n * FP + 2 * fq) = o;
}

// ---- warp-level bitonic sort on 32-bit items, zero barriers -----------------
template<int NR>
__device__ __forceinline__ void warp_bitonic32(unsigned (&v)[NR], unsigned lane) {
    const unsigned N = NR * 32;
#pragma unroll
    for (unsigned k = 2; k <= N; k <<= 1) {
#pragma unroll
        for (unsigned j = N >> 1; j > 0; j >>= 1) {
            if (j >= k) continue;   // compile-time pruned
            if (j >= 32) {
                unsigned rj = j >> 5;
#pragma unroll
                for (int r = 0; r < NR; r++) {
                    if ((r & (int)rj) == 0 && (r ^ (int)rj) < NR) {
                        int r2 = r ^ (int)rj;
                        unsigned ia = r * 32 + lane;
                        bool up = ((ia & k) == 0);
                        unsigned a = v[r], b = v[r2];
                        if ((a > b) == up) { v[r] = b; v[r2] = a; }
                    }
                }
            } else {
#pragma unroll
                for (int r = 0; r < NR; r++) {
                    unsigned i = r * 32 + lane;
                    unsigned x = v[r];
                    unsigned y = __shfl_xor_sync(~0u, x, j);
                    bool up = ((i & k) == 0);
                    bool keepmin = (((lane & j) == 0) == up);
                    v[r] = keepmin ? (x < y ? x : y) : (x > y ? x : y);
                }
            }
        }
    }
}

template<int NR>
__device__ __forceinline__ void sort_bucket(unsigned b, unsigned count, unsigned lane) {
    size_t start = (size_t)b * MAXB;
    unsigned v[NR];
#pragma unroll
    for (int r = 0; r < NR; r++) {
        unsigned i = r * 32 + lane;
        if (i < count) {
            unsigned key = (unsigned)(g_bkt[start + i] >> 32);
            v[r] = ((key & 0xFFFFu) << 7) | i;     // col<<7 | slot
        } else v[r] = 0xFFFFFFFFu;
    }
    warp_bitonic32<NR>(v, lane);

    unsigned mask[NR];
    unsigned prev_last = 0xFFFFFFFFu;
#pragma unroll
    for (int r = 0; r < NR; r++) {
        unsigned p = __shfl_up_sync(~0u, v[r], 1);
        unsigned last = __shfl_sync(~0u, v[r], 31);
        if (lane == 0) p = prev_last;
        unsigned i = r * 32 + lane;
        bool head = (i < count) && ((i == 0) || ((p >> 7) != (v[r] >> 7)));
        mask[r] = __ballot_sync(~0u, head);
        prev_last = last;
    }
    unsigned base = 0;
#pragma unroll
    for (int r = 0; r < NR; r++) {
        unsigned i = r * 32 + lane;
        if (i < count) {
            unsigned head = (mask[r] >> lane) & 1u;
            unsigned lr = base + __popc(mask[r] & ((1u << lane) - 1u));
            g_ms[start + i] = (unsigned short)((head << 15) | (lr << 8) | (v[r] & 0x7Fu));
        }
        base += __popc(mask[r]);
    }
    if (lane == 0) g_dcnt[b] = base;
}

// ---------------- kernels ----------------------------------------------------

// dtype sniff, single warp: int64 values < 2^31 => every high word is 0.
__global__ void k_detect(const int2* __restrict__ ei) {
    unsigned lane = threadIdx.x;
    bool nz = false;
#pragma unroll
    for (int k = 0; k < 8; k++) nz |= (ei[lane * 8 + k].y != 0);
    unsigned m = __ballot_sync(~0u, nz);
    if (lane == 0) g_is32 = (m != 0) ? 1 : 0;
}

// K1: 1-in-3 blocks scatter, 2-in-3 blocks do first half of xpool
#define P1_GRID (8192 * 3)
__global__ __launch_bounds__(256) void k_p1(const void* __restrict__ eiv,
                                            const float* __restrict__ x,
                                            float* __restrict__ out) {
    unsigned bid = blockIdx.x;
    if (bid % 3 == 0) {
        unsigned e = (bid / 3) * 256 + threadIdx.x;
        if (e >= EE) return;
        unsigned r, c;
        if (g_is32) {
            const int* ei = (const int*)eiv;
            r = (unsigned)ei[e]; c = (unsigned)ei[EE + e];
        } else {
            const long long* ei = (const long long*)eiv;
            r = (unsigned)ei[e]; c = (unsigned)ei[EE + e];
        }
        unsigned key = ((r >> 1) << 16) | (c >> 1);
        unsigned b = key >> 16;
        unsigned pos = atomicAdd(&g_cnt[b], 1u);
        if (pos < MAXB)
            g_bkt[(size_t)b * MAXB + pos] = ((unsigned long long)key << 32) | (unsigned)e;
    } else {
        unsigned xid = bid - bid / 3 - 1;          // 0 .. 16383
        xpool_chunk(xid * 256 + threadIdx.x, x, out);
    }
}

// K2: 1-in-3 blocks sort (8 buckets/block), 2-in-3 blocks do second half of xpool
#define P2_GRID (8192 * 3)
__global__ __launch_bounds__(256) void k_p2(const float* __restrict__ x,
                                            float* __restrict__ out) {
    unsigned bid = blockIdx.x;
    if (bid % 3 == 0) {
        unsigned lane = threadIdx.x & 31;
        unsigned b = (bid / 3) * 8 + (threadIdx.x >> 5);
        unsigned count = g_cnt[b];
        if (count == 0) { if (lane == 0) g_dcnt[b] = 0; return; }
        if (count > MAXB) count = MAXB;   // statistically impossible; safety
        if (count <= 64) sort_bucket<2>(b, count, lane);
        else             sort_bucket<4>(b, count, lane);
    } else {
        unsigned xid = (bid - bid / 3 - 1) + 16384; // 16384 .. 32767
        xpool_chunk(xid * 256 + threadIdx.x, x, out);
    }
}

// ---- 3-stage parallel 64K exclusive scan over g_dcnt -> g_doff --------------
__global__ __launch_bounds__(256) void k_scanA() {
    __shared__ unsigned ws[8];
    int tid = threadIdx.x;
    unsigned v = g_dcnt[blockIdx.x * 256 + tid];
#pragma unroll
    for (int off = 16; off; off >>= 1) v += __shfl_down_sync(~0u, v, off);
    if ((tid & 31) == 0) ws[tid >> 5] = v;
    __syncthreads();
    if (tid == 0) {
        unsigned s = 0;
#pragma unroll
        for (int w = 0; w < 8; w++) s += ws[w];
        g_part[blockIdx.x] = s;
    }
}

__global__ __launch_bounds__(256) void k_scanB() {
    __shared__ unsigned ws[8];
    int tid = threadIdx.x;
    int lane = tid & 31, wid = tid >> 5;
    unsigned x = g_part[tid];
    unsigned v = x;
#pragma unroll
    for (int off = 1; off < 32; off <<= 1) {
        unsigned t = __shfl_up_sync(~0u, v, off);
        if (lane >= off) v += t;
    }
    if (lane == 31) ws[wid] = v;
    __syncthreads();
    if (wid == 0 && lane < 8) {
        unsigned w = ws[lane];
#pragma unroll
        for (int off = 1; off < 8; off <<= 1) {
            unsigned t = __shfl_up_sync(0xffu, w, off);
            if (lane >= off) w += t;
        }
        ws[lane] = w;
    }
    __syncthreads();
    unsigned excl = v - x + (wid > 0 ? ws[wid - 1] : 0u);
    g_partoff[tid] = excl;
    if (tid == 255) g_totalU = excl + x;
}

__global__ __launch_bounds__(256) void k_scanC() {
    __shared__ unsigned ws[8];
    int tid = threadIdx.x;
    int lane = tid & 31, wid = tid >> 5;
    int i = blockIdx.x * 256 + tid;
    unsigned x = g_dcnt[i];
    unsigned v = x;
#pragma unroll
    for (int off = 1; off < 32; off <<= 1) {
        unsigned t = __shfl_up_sync(~0u, v, off);
        if (lane >= off) v += t;
    }
    if (lane == 31) ws[wid] = v;
    __syncthreads();
    if (wid == 0 && lane < 8) {
        unsigned w = ws[lane];
#pragma unroll
        for (int off = 1; off < 8; off <<= 1) {
            unsigned t = __shfl_up_sync(0xffu, w, off);
            if (lane >= off) w += t;
        }
        ws[lane] = w;
    }
    __syncthreads();
    g_doff[i] = g_partoff[blockIdx.x] + v - x + (wid > 0 ? ws[wid - 1] : 0u);
}

// fat tail: runs (warp/bucket) + pad + batch
#define TAIL_GRID (8192 + 8192 + 256)
__global__ __launch_bounds__(256) void k_tail(const float* __restrict__ ea,
                                              float* __restrict__ out) {
    unsigned bid = blockIdx.x;
    if (bid < 8192) {
        unsigned lane = threadIdx.x & 31;
        unsigned b = bid * 8 + (threadIdx.x >> 5);
        unsigned count = g_cnt[b];
        if (count > MAXB) count = MAXB;
        if (count == 0) return;
        size_t start = (size_t)b * MAXB;
        unsigned doff = g_doff[b];
        for (unsigned i0 = 0; i0 < count; i0 += 32) {
            unsigned i = i0 + lane;
            if (i >= count) break;
            unsigned ms = g_ms[start + i];
            if (!(ms & 0x8000u)) continue;         // not a run head
            unsigned rank = doff + ((ms >> 8) & 0x7Fu);
            unsigned long long p = g_bkt[start + (ms & 0x7Fu)];
            unsigned key = (unsigned)(p >> 32);
            const float4* row = (const float4*)(ea + (size_t)(unsigned)p * DA);
            float4 a0 = row[0], a1 = row[1], a2 = row[2], a3 = row[3];
            unsigned j = i + 1;
            while (j < count) {
                unsigned ms2 = g_ms[start + j];
                if (ms2 & 0x8000u) break;
                unsigned long long p2 = g_bkt[start + (ms2 & 0x7Fu)];
                const float4* r2 = (const float4*)(ea + (size_t)(unsigned)p2 * DA);
                float4 b0 = r2[0], b1 = r2[1], b2 = r2[2], b3 = r2[3];
                a0.x += b0.x; a0.y += b0.y; a0.z += b0.z; a0.w += b0.w;
                a1.x += b1.x; a1.y += b1.y; a1.z += b1.z; a1.w += b1.w;
                a2.x += b2.x; a2.y += b2.y; a2.z += b2.z; a2.w += b2.w;
                a3.x += b3.x; a3.y += b3.y; a3.z += b3.z; a3.w += b3.w;
                j++;
            }
            float4* eao = (float4*)(out + EA_OFF + (size_t)rank * DA);
            eao[0] = a0; eao[1] = a1; eao[2] = a2; eao[3] = a3;
            out[EI_OFF + rank]      = (float)(key >> 16);
            out[EI_OFF + EE + rank] = (float)(key & 0xFFFFu);
        }
    } else if (bid < 16384) {
        unsigned U = g_totalU;
        unsigned r = (bid - 8192) * 256 + threadIdx.x;
        if (r >= EE || r < U) return;
        out[EI_OFF + r]      = 65536.0f;
        out[EI_OFF + EE + r] = 0.0f;
        float4 z = {0, 0, 0, 0};
        float4* eao = (float4*)(out + EA_OFF + (size_t)r * DA);
        eao[0] = z; eao[1] = z; eao[2] = z; eao[3] = z;
    } else {
        unsigned n = (bid - 16384) * 256 + threadIdx.x;
        if (n < NPOOL) out[BP_OFF + n] = (float)(n >> 10);
    }
}

// ---------------- launch ------------------------------------------------------

extern "C" void kernel_launch(void* const* d_in, const int* in_sizes, int n_in,
                              void* d_out, int out_size) {
    const float* x  = (const float*)d_in[0];
    const float* ea = (const float*)d_in[1];
    const void*  ei = d_in[2];
    float* out = (float*)d_out;

    unsigned* d_cnt; cudaGetSymbolAddress((void**)&d_cnt, g_cnt);
    cudaMemsetAsync(d_cnt, 0, NB * sizeof(unsigned));
    k_detect<<<1, 32>>>((const int2*)ei);
    k_p1<<<P1_GRID, 256>>>(ei, x, out);
    k_p2<<<P2_GRID, 256>>>(x, out);
    k_scanA<<<256, 256>>>();
    k_scanB<<<1, 256>>>();
    k_scanC<<<256, 256>>>();
    k_tail<<<TAIL_GRID, 256>>>(ea, out);
}